// round 11
// baseline (speedup 1.0000x reference)
#include <cuda_runtime.h>

// End2End_7645041787474 — R11: R9 config + 2-way heavy-row split for tail balance.
//
// Math collapse (R1): forward g == one_hot(argmax(logits+gumbel)); each output
// row is one W row (or zeros); nn_idx is that row's own index (or 0).
//
// Steady state (R9/R10): 19.2us, flat under DRAM-byte reduction -> binder is
// tail quantization (512 heavy CTAs/148 SMs = 3.46 -> ~16% tail loss).
// R11: each heavy row -> 2 half-row CTAs (1024 heavy halves, 6.9/SM, ~1.5%
// tail). Halves combine via private key slots + per-row counter; the last
// arriving half decodes and writes. Counter returns to 0 (replay-safe).

namespace {
constexpr int Bc  = 8;
constexpr int Lc  = 128;
constexpr int VFc = 32128;
constexpr int Vc  = 32100;
constexpr int Dc  = 768;
constexpr int NROWS = Bc * Lc;        // 1024
constexpr int NT  = 256;
constexpr int N8  = VFc / 8;          // 4016 8-float groups per row per stream
constexpr int HALF8 = N8 / 2;         // 2008 per half
}

__device__ unsigned long long g_key[NROWS * 2];
__device__ int g_cnt[NROWS];          // zero-init; returns to zero each replay

__device__ __forceinline__ unsigned long long pack_key(float v, int idx) {
    unsigned u = __float_as_uint(v);
    u = (u & 0x80000000u) ? ~u : (u | 0x80000000u);   // monotone float -> u32
    return ((unsigned long long)u << 32) | (unsigned)(~(unsigned)idx);
}

struct f8 { float v[8]; };

__device__ __forceinline__ f8 ld32_first(const float* p) {
    unsigned r0,r1,r2,r3,r4,r5,r6,r7;
    asm volatile("ld.global.nc.L2::evict_first.v8.b32 {%0,%1,%2,%3,%4,%5,%6,%7}, [%8];"
                 : "=r"(r0),"=r"(r1),"=r"(r2),"=r"(r3),
                   "=r"(r4),"=r"(r5),"=r"(r6),"=r"(r7) : "l"(p));
    f8 o;
    o.v[0]=__uint_as_float(r0); o.v[1]=__uint_as_float(r1);
    o.v[2]=__uint_as_float(r2); o.v[3]=__uint_as_float(r3);
    o.v[4]=__uint_as_float(r4); o.v[5]=__uint_as_float(r5);
    o.v[6]=__uint_as_float(r6); o.v[7]=__uint_as_float(r7);
    return o;
}
__device__ __forceinline__ f8 ld32_last(const float* p) {
    unsigned r0,r1,r2,r3,r4,r5,r6,r7;
    asm volatile("ld.global.nc.L2::evict_last.v8.b32 {%0,%1,%2,%3,%4,%5,%6,%7}, [%8];"
                 : "=r"(r0),"=r"(r1),"=r"(r2),"=r"(r3),
                   "=r"(r4),"=r"(r5),"=r"(r6),"=r"(r7) : "l"(p));
    f8 o;
    o.v[0]=__uint_as_float(r0); o.v[1]=__uint_as_float(r1);
    o.v[2]=__uint_as_float(r2); o.v[3]=__uint_as_float(r3);
    o.v[4]=__uint_as_float(r4); o.v[5]=__uint_as_float(r5);
    o.v[6]=__uint_as_float(r6); o.v[7]=__uint_as_float(r7);
    return o;
}
__device__ __forceinline__ void st32_stream(float* p, const f8& d) {
    asm volatile("st.global.cs.v8.b32 [%0], {%1,%2,%3,%4,%5,%6,%7,%8};"
                 :: "l"(p),
                    "r"(__float_as_uint(d.v[0])), "r"(__float_as_uint(d.v[1])),
                    "r"(__float_as_uint(d.v[2])), "r"(__float_as_uint(d.v[3])),
                    "r"(__float_as_uint(d.v[4])), "r"(__float_as_uint(d.v[5])),
                    "r"(__float_as_uint(d.v[6])), "r"(__float_as_uint(d.v[7])));
}

template <bool PIN_LOGITS>
__device__ __forceinline__ void argmax_half(const float* __restrict__ lp,
                                            const float* __restrict__ gp,
                                            int j0, int tid,
                                            unsigned long long& key_out)
{
    float vb[8];
    int   ib[8];
    #pragma unroll
    for (int e = 0; e < 8; e++) { vb[e] = -3.402823466e38f; ib[e] = 0x7fffffff; }

    #pragma unroll 2
    for (int j = j0 + tid; j < j0 + HALF8; j += NT) {
        const f8 a = PIN_LOGITS ? ld32_last(lp + (size_t)j * 8)
                                : ld32_first(lp + (size_t)j * 8);
        const f8 c = ld32_last(gp + (size_t)j * 8);   // gumbel: always pinned
        const int base = j << 3;
        #pragma unroll
        for (int e = 0; e < 8; e++) {
            const float z = a.v[e] + c.v[e];
            // strict '>' within ascending per-tracker scan: lowest index
            if (z > vb[e]) { vb[e] = z; ib[e] = base + e; }
        }
    }
    unsigned long long key = 0ULL;
    #pragma unroll
    for (int e = 0; e < 8; e++) {
        const unsigned long long k = pack_key(vb[e], ib[e]);
        if (k > key) key = k;
    }
    key_out = key;
}

__global__ __launch_bounds__(NT)
void fused_gsm_embed_nn(const float* __restrict__ logits,
                        const float* __restrict__ gumbel,
                        const float* __restrict__ wemb,
                        const int*   __restrict__ rwrt,
                        const int*   __restrict__ psg,
                        float*       __restrict__ out)
{
    // interleaved row index; two consecutive blockIdx share one row
    const int idx   = blockIdx.x >> 1;
    const int chunk = blockIdx.x & 1;
    const int b     = idx & 7;
    const int l     = idx >> 3;
    const int row   = (b << 7) | l;
    const int tid   = threadIdx.x;

    __shared__ unsigned long long s_key[NT / 32];
    __shared__ int s_src, s_nn, s_last;
    __shared__ int s_red[NT];

    if (rwrt[row]) {
        const float* lp = logits + (size_t)row * VFc;
        const float* gp = gumbel + (size_t)row * VFc;

        unsigned long long key;
        if (b == 0) argmax_half<true >(lp, gp, chunk * HALF8, tid, key);
        else        argmax_half<false>(lp, gp, chunk * HALF8, tid, key);

        #pragma unroll
        for (int off = 16; off > 0; off >>= 1) {
            const unsigned long long o = __shfl_down_sync(0xffffffffu, key, off);
            if (o > key) key = o;
        }
        if ((tid & 31) == 0) s_key[tid >> 5] = key;
        __syncthreads();
        if (tid == 0) {
            #pragma unroll
            for (int w = 1; w < NT / 32; w++)
                if (s_key[w] > key) key = s_key[w];
            g_key[(row << 1) | chunk] = key;
            __threadfence();
            const int old = atomicAdd(&g_cnt[row], 1);
            s_last = (old == 1);
        }
        __syncthreads();
        if (!s_last) return;                         // first half done

        if (tid == 0) {
            g_cnt[row] = 0;                          // replay-safe reset
            unsigned long long best = g_key[row << 1];
            const unsigned long long o = g_key[(row << 1) | 1];
            if (o > best) best = o;
            const int g = (int)(~(unsigned)(best & 0xffffffffu));
            s_src = (g < Vc) ? g : -1;   // g >= V => zero row (g[..., :V])
            s_nn  = (g < Vc) ? g : 0;    // zero row => sims all 0 => argmax 0
        }
        __syncthreads();
    } else {
        if (chunk) return;                           // light rows: one CTA only
        // ---- psg path: len[b] = sum of prefix mask ----
        s_red[tid] = (tid < Lc) ? rwrt[b * Lc + tid] : 0;
        __syncthreads();
        #pragma unroll
        for (int s = NT / 2; s > 0; s >>= 1) {
            if (tid < s) s_red[tid] += s_red[tid + s];
            __syncthreads();
        }
        if (tid == 0) {
            const int len = s_red[0];
            const int idx2 = psg[b * Lc + (l - len)];
            s_src = idx2;
            s_nn  = idx2;
        }
        __syncthreads();
    }

    // ---- write embeds row: 96 threads x 32B; gather pinned, store streaming ----
    const int src = s_src;
    float* orow = out + (size_t)row * Dc;
    if (tid < Dc / 8) {               // 96 threads
        f8 d;
        if (src >= 0) {
            d = ld32_last(wemb + (size_t)src * Dc + tid * 8);   // reused per replay
        } else {
            #pragma unroll
            for (int e = 0; e < 8; e++) d.v[e] = 0.f;
        }
        st32_stream(orow + tid * 8, d);   // output: evict-first
    }
    if (tid == 0)
        out[(size_t)NROWS * Dc + row] = (float)s_nn;
}

extern "C" void kernel_launch(void* const* d_in, const int* in_sizes, int n_in,
                              void* d_out, int out_size) {
    const float* logits = (const float*)d_in[0];
    const float* gumbel = (const float*)d_in[1];
    const float* wemb   = (const float*)d_in[2];
    const int*   rwrt   = (const int*)d_in[3];
    const int*   psg    = (const int*)d_in[4];
    float*       out    = (float*)d_out;

    fused_gsm_embed_nn<<<NROWS * 2, NT>>>(logits, gumbel, wemb, rwrt, psg, out);
}

// round 12
// speedup vs baseline: 1.0198x; 1.0198x over previous
#include <cuda_runtime.h>

// End2End_7645041787474 — R12: R10 anchor (19.2us) + deeper per-thread MLP.
//
// Math collapse (R1): forward g == one_hot(argmax(logits+gumbel)); each output
// row is one W row (or zeros); nn_idx is that row's own index (or 0).
//
// Session model:
//   - L2 residency via evict_last (gumbel + logits b<2, ~82MB) survives graph
//     replays: steady 19.2us vs 28us cold (R7/R9/R10).
//   - DRAM-byte reduction flat (R10); grid>~1184 -> 2 waves, regression (R11).
// R12: keep grid=1024 single wave; widen per-thread pipeline to unroll-4
// (8 outstanding v8.b32 loads/thread) to shrink per-CTA ramp+drain.

namespace {
constexpr int Bc  = 8;
constexpr int Lc  = 128;
constexpr int VFc = 32128;
constexpr int Vc  = 32100;
constexpr int Dc  = 768;
constexpr int NROWS = Bc * Lc;        // 1024
constexpr int NT  = 256;
constexpr int N8  = VFc / 8;          // 4016 8-float groups per row per stream
}

__device__ __forceinline__ unsigned long long pack_key(float v, int idx) {
    unsigned u = __float_as_uint(v);
    u = (u & 0x80000000u) ? ~u : (u | 0x80000000u);   // monotone float -> u32
    return ((unsigned long long)u << 32) | (unsigned)(~(unsigned)idx);
}

struct f8 { float v[8]; };

__device__ __forceinline__ f8 ld32_first(const float* p) {
    unsigned r0,r1,r2,r3,r4,r5,r6,r7;
    asm volatile("ld.global.nc.L2::evict_first.v8.b32 {%0,%1,%2,%3,%4,%5,%6,%7}, [%8];"
                 : "=r"(r0),"=r"(r1),"=r"(r2),"=r"(r3),
                   "=r"(r4),"=r"(r5),"=r"(r6),"=r"(r7) : "l"(p));
    f8 o;
    o.v[0]=__uint_as_float(r0); o.v[1]=__uint_as_float(r1);
    o.v[2]=__uint_as_float(r2); o.v[3]=__uint_as_float(r3);
    o.v[4]=__uint_as_float(r4); o.v[5]=__uint_as_float(r5);
    o.v[6]=__uint_as_float(r6); o.v[7]=__uint_as_float(r7);
    return o;
}
__device__ __forceinline__ f8 ld32_last(const float* p) {
    unsigned r0,r1,r2,r3,r4,r5,r6,r7;
    asm volatile("ld.global.nc.L2::evict_last.v8.b32 {%0,%1,%2,%3,%4,%5,%6,%7}, [%8];"
                 : "=r"(r0),"=r"(r1),"=r"(r2),"=r"(r3),
                   "=r"(r4),"=r"(r5),"=r"(r6),"=r"(r7) : "l"(p));
    f8 o;
    o.v[0]=__uint_as_float(r0); o.v[1]=__uint_as_float(r1);
    o.v[2]=__uint_as_float(r2); o.v[3]=__uint_as_float(r3);
    o.v[4]=__uint_as_float(r4); o.v[5]=__uint_as_float(r5);
    o.v[6]=__uint_as_float(r6); o.v[7]=__uint_as_float(r7);
    return o;
}
__device__ __forceinline__ void st32_stream(float* p, const f8& d) {
    asm volatile("st.global.cs.v8.b32 [%0], {%1,%2,%3,%4,%5,%6,%7,%8};"
                 :: "l"(p),
                    "r"(__float_as_uint(d.v[0])), "r"(__float_as_uint(d.v[1])),
                    "r"(__float_as_uint(d.v[2])), "r"(__float_as_uint(d.v[3])),
                    "r"(__float_as_uint(d.v[4])), "r"(__float_as_uint(d.v[5])),
                    "r"(__float_as_uint(d.v[6])), "r"(__float_as_uint(d.v[7])));
}

template <bool PIN_LOGITS>
__device__ __forceinline__ void argmax_body(const float* __restrict__ lp,
                                            const float* __restrict__ gp,
                                            int tid,
                                            unsigned long long& key_out)
{
    float vb[8];
    int   ib[8];
    #pragma unroll
    for (int e = 0; e < 8; e++) { vb[e] = -3.402823466e38f; ib[e] = 0x7fffffff; }

    // N8 = 4016, NT = 256 -> 15 full strides + 1 partial (176 threads).
    // Software-pipelined x4: batch 4 iterations' loads (8 v8 loads in flight),
    // then do the compare work. Trackers stay per-lane monotone (ascending j),
    // so strict '>' keeps the lowest index; cross-tracker ties via ~idx key.
    constexpr int FULL = (N8 / NT) & ~3;          // 12 strides in x4 groups
    int j = tid;
    #pragma unroll 1
    for (int s = 0; s < FULL / 4; s++) {
        f8 a0, a1, a2, a3, c0, c1, c2, c3;
        const float* l0 = lp + (size_t)j * 8;
        const float* g0 = gp + (size_t)j * 8;
        if (PIN_LOGITS) {
            a0 = ld32_last(l0);
            a1 = ld32_last(l0 + (size_t)NT * 8);
            a2 = ld32_last(l0 + (size_t)2 * NT * 8);
            a3 = ld32_last(l0 + (size_t)3 * NT * 8);
        } else {
            a0 = ld32_first(l0);
            a1 = ld32_first(l0 + (size_t)NT * 8);
            a2 = ld32_first(l0 + (size_t)2 * NT * 8);
            a3 = ld32_first(l0 + (size_t)3 * NT * 8);
        }
        c0 = ld32_last(g0);
        c1 = ld32_last(g0 + (size_t)NT * 8);
        c2 = ld32_last(g0 + (size_t)2 * NT * 8);
        c3 = ld32_last(g0 + (size_t)3 * NT * 8);

        const f8* as[4] = {&a0, &a1, &a2, &a3};
        const f8* cs[4] = {&c0, &c1, &c2, &c3};
        #pragma unroll
        for (int k = 0; k < 4; k++) {
            const int base = (j + k * NT) << 3;
            #pragma unroll
            for (int e = 0; e < 8; e++) {
                const float z = as[k]->v[e] + cs[k]->v[e];
                if (z > vb[e]) { vb[e] = z; ib[e] = base + e; }
            }
        }
        j += 4 * NT;
    }
    // remainder strides (3 full + possible partial)
    #pragma unroll 1
    for (; j < N8; j += NT) {
        const f8 a = PIN_LOGITS ? ld32_last(lp + (size_t)j * 8)
                                : ld32_first(lp + (size_t)j * 8);
        const f8 c = ld32_last(gp + (size_t)j * 8);
        const int base = j << 3;
        #pragma unroll
        for (int e = 0; e < 8; e++) {
            const float z = a.v[e] + c.v[e];
            if (z > vb[e]) { vb[e] = z; ib[e] = base + e; }
        }
    }

    unsigned long long key = 0ULL;
    #pragma unroll
    for (int e = 0; e < 8; e++) {
        const unsigned long long k = pack_key(vb[e], ib[e]);
        if (k > key) key = k;
    }
    key_out = key;
}

__global__ __launch_bounds__(NT)
void fused_gsm_embed_nn(const float* __restrict__ logits,
                        const float* __restrict__ gumbel,
                        const float* __restrict__ wemb,
                        const int*   __restrict__ rwrt,
                        const int*   __restrict__ psg,
                        float*       __restrict__ out)
{
    // batch-interleaved mapping: heavy rows form a contiguous blockIdx prefix
    const int b   = blockIdx.x & 7;
    const int l   = blockIdx.x >> 3;
    const int row = (b << 7) | l;
    const int tid = threadIdx.x;

    __shared__ unsigned long long s_key[NT / 32];
    __shared__ int s_src, s_nn;
    __shared__ int s_red[NT];

    if (rwrt[row]) {
        const float* lp = logits + (size_t)row * VFc;
        const float* gp = gumbel + (size_t)row * VFc;

        unsigned long long key;
        if (b < 2) argmax_body<true >(lp, gp, tid, key);  // pin batches 0,1 logits
        else       argmax_body<false>(lp, gp, tid, key);  // stream logits

        #pragma unroll
        for (int off = 16; off > 0; off >>= 1) {
            const unsigned long long o = __shfl_down_sync(0xffffffffu, key, off);
            if (o > key) key = o;
        }
        if ((tid & 31) == 0) s_key[tid >> 5] = key;
        __syncthreads();
        if (tid == 0) {
            #pragma unroll
            for (int w = 1; w < NT / 32; w++)
                if (s_key[w] > key) key = s_key[w];
            const int g = (int)(~(unsigned)(key & 0xffffffffu));
            s_src = (g < Vc) ? g : -1;   // g >= V => zero row (g[..., :V])
            s_nn  = (g < Vc) ? g : 0;    // zero row => sims all 0 => argmax 0
        }
        __syncthreads();
    } else {
        // ---- psg path: len[b] = sum of prefix mask ----
        s_red[tid] = (tid < Lc) ? rwrt[b * Lc + tid] : 0;
        __syncthreads();
        #pragma unroll
        for (int s = NT / 2; s > 0; s >>= 1) {
            if (tid < s) s_red[tid] += s_red[tid + s];
            __syncthreads();
        }
        if (tid == 0) {
            const int len = s_red[0];
            const int idx = psg[b * Lc + (l - len)];
            s_src = idx;
            s_nn  = idx;
        }
        __syncthreads();
    }

    // ---- write embeds row: 96 threads x 32B; gather pinned, store streaming ----
    const int src = s_src;
    float* orow = out + (size_t)row * Dc;
    if (tid < Dc / 8) {               // 96 threads
        f8 d;
        if (src >= 0) {
            d = ld32_last(wemb + (size_t)src * Dc + tid * 8);   // reused per replay
        } else {
            #pragma unroll
            for (int e = 0; e < 8; e++) d.v[e] = 0.f;
        }
        st32_stream(orow + tid * 8, d);   // output: evict-first
    }
    if (tid == 0)
        out[(size_t)NROWS * Dc + row] = (float)s_nn;
}

extern "C" void kernel_launch(void* const* d_in, const int* in_sizes, int n_in,
                              void* d_out, int out_size) {
    const float* logits = (const float*)d_in[0];
    const float* gumbel = (const float*)d_in[1];
    const float* wemb   = (const float*)d_in[2];
    const int*   rwrt   = (const int*)d_in[3];
    const int*   psg    = (const int*)d_in[4];
    float*       out    = (float*)d_out;

    fused_gsm_embed_nn<<<NROWS, NT>>>(logits, gumbel, wemb, rwrt, psg, out);
}

// round 13
// speedup vs baseline: 1.0976x; 1.0762x over previous
#include <cuda_runtime.h>

// End2End_7645041787474 — R13: R10 anchor + low-register tree-max argmax.
//
// Math collapse (R1): forward g == one_hot(argmax(logits+gumbel)); each output
// row is one W row (or zeros); nn_idx is that row's own index (or 0).
//
// Session model:
//   - L2 residency (evict_last: gumbel + logits b<2 + wemb) survives graph
//     replays -> steady 19.2us vs 28us cold.
//   - Regime is LATENCY-bound: BW ~ warps x in-flight/warp. R12 (more
//     in-flight, fewer warps) lost; R13 raises warps at constant in-flight:
//     per-stride tree-max + (bestv,bestj) scalar tracker cuts ~14 regs ->
//     higher occupancy. Winning lane recovered by one deterministic recompute.

namespace {
constexpr int Bc  = 8;
constexpr int Lc  = 128;
constexpr int VFc = 32128;
constexpr int Vc  = 32100;
constexpr int Dc  = 768;
constexpr int NROWS = Bc * Lc;        // 1024
constexpr int NT  = 256;
constexpr int N8  = VFc / 8;          // 4016 8-float groups per row per stream
}

__device__ __forceinline__ unsigned long long pack_key(float v, int idx) {
    unsigned u = __float_as_uint(v);
    u = (u & 0x80000000u) ? ~u : (u | 0x80000000u);   // monotone float -> u32
    return ((unsigned long long)u << 32) | (unsigned)(~(unsigned)idx);
}

struct f8 { float v[8]; };

__device__ __forceinline__ f8 ld32_first(const float* p) {
    unsigned r0,r1,r2,r3,r4,r5,r6,r7;
    asm volatile("ld.global.nc.L2::evict_first.v8.b32 {%0,%1,%2,%3,%4,%5,%6,%7}, [%8];"
                 : "=r"(r0),"=r"(r1),"=r"(r2),"=r"(r3),
                   "=r"(r4),"=r"(r5),"=r"(r6),"=r"(r7) : "l"(p));
    f8 o;
    o.v[0]=__uint_as_float(r0); o.v[1]=__uint_as_float(r1);
    o.v[2]=__uint_as_float(r2); o.v[3]=__uint_as_float(r3);
    o.v[4]=__uint_as_float(r4); o.v[5]=__uint_as_float(r5);
    o.v[6]=__uint_as_float(r6); o.v[7]=__uint_as_float(r7);
    return o;
}
__device__ __forceinline__ f8 ld32_last(const float* p) {
    unsigned r0,r1,r2,r3,r4,r5,r6,r7;
    asm volatile("ld.global.nc.L2::evict_last.v8.b32 {%0,%1,%2,%3,%4,%5,%6,%7}, [%8];"
                 : "=r"(r0),"=r"(r1),"=r"(r2),"=r"(r3),
                   "=r"(r4),"=r"(r5),"=r"(r6),"=r"(r7) : "l"(p));
    f8 o;
    o.v[0]=__uint_as_float(r0); o.v[1]=__uint_as_float(r1);
    o.v[2]=__uint_as_float(r2); o.v[3]=__uint_as_float(r3);
    o.v[4]=__uint_as_float(r4); o.v[5]=__uint_as_float(r5);
    o.v[6]=__uint_as_float(r6); o.v[7]=__uint_as_float(r7);
    return o;
}
__device__ __forceinline__ void st32_stream(float* p, const f8& d) {
    asm volatile("st.global.cs.v8.b32 [%0], {%1,%2,%3,%4,%5,%6,%7,%8};"
                 :: "l"(p),
                    "r"(__float_as_uint(d.v[0])), "r"(__float_as_uint(d.v[1])),
                    "r"(__float_as_uint(d.v[2])), "r"(__float_as_uint(d.v[3])),
                    "r"(__float_as_uint(d.v[4])), "r"(__float_as_uint(d.v[5])),
                    "r"(__float_as_uint(d.v[6])), "r"(__float_as_uint(d.v[7])));
}

// max of the 8 elementwise sums (no NaN in this data; fmaxf tree)
__device__ __forceinline__ float stride_max(const f8& a, const f8& c) {
    const float z0 = fmaxf(a.v[0] + c.v[0], a.v[1] + c.v[1]);
    const float z1 = fmaxf(a.v[2] + c.v[2], a.v[3] + c.v[3]);
    const float z2 = fmaxf(a.v[4] + c.v[4], a.v[5] + c.v[5]);
    const float z3 = fmaxf(a.v[6] + c.v[6], a.v[7] + c.v[7]);
    return fmaxf(fmaxf(z0, z1), fmaxf(z2, z3));
}

template <bool PIN_LOGITS>
__device__ __forceinline__ void argmax_body(const float* __restrict__ lp,
                                            const float* __restrict__ gp,
                                            int tid,
                                            unsigned long long& key_out)
{
    float bestv = -3.402823466e38f;
    int   bestj = -1;

    // N8 = 4016: 14 strides in x2 groups, then strides 14 and (partial) 15.
    constexpr int FULL2 = (N8 / NT) & ~1;     // 14
    int j = tid;
    #pragma unroll 1
    for (int s = 0; s < FULL2 / 2; s++) {
        const f8 a0 = PIN_LOGITS ? ld32_last(lp + (size_t)j * 8)
                                 : ld32_first(lp + (size_t)j * 8);
        const f8 c0 = ld32_last(gp + (size_t)j * 8);
        const f8 a1 = PIN_LOGITS ? ld32_last(lp + (size_t)(j + NT) * 8)
                                 : ld32_first(lp + (size_t)(j + NT) * 8);
        const f8 c1 = ld32_last(gp + (size_t)(j + NT) * 8);

        const float m0 = stride_max(a0, c0);
        const float m1 = stride_max(a1, c1);
        // strict '>' in ascending stride order keeps the EARLIEST stride
        if (m0 > bestv) { bestv = m0; bestj = j;      }
        if (m1 > bestv) { bestv = m1; bestj = j + NT; }
        j += 2 * NT;
    }
    #pragma unroll 1
    for (; j < N8; j += NT) {
        const f8 a = PIN_LOGITS ? ld32_last(lp + (size_t)j * 8)
                                : ld32_first(lp + (size_t)j * 8);
        const f8 c = ld32_last(gp + (size_t)j * 8);
        const float m = stride_max(a, c);
        if (m > bestv) { bestv = m; bestj = j; }
    }

    // recover lowest lane within the winning stride (deterministic replay;
    // data is L1/L2-hot). Descending scan with '==' leaves the LOWEST e.
    int besti = 0x7fffffff;
    if (bestj >= 0) {
        const f8 a = PIN_LOGITS ? ld32_last(lp + (size_t)bestj * 8)
                                : ld32_first(lp + (size_t)bestj * 8);
        const f8 c = ld32_last(gp + (size_t)bestj * 8);
        #pragma unroll
        for (int e = 7; e >= 0; e--)
            if (a.v[e] + c.v[e] == bestv) besti = (bestj << 3) + e;
    }
    key_out = pack_key(bestv, besti);
}

__global__ __launch_bounds__(NT, 6)
void fused_gsm_embed_nn(const float* __restrict__ logits,
                        const float* __restrict__ gumbel,
                        const float* __restrict__ wemb,
                        const int*   __restrict__ rwrt,
                        const int*   __restrict__ psg,
                        float*       __restrict__ out)
{
    // batch-interleaved mapping: heavy rows form a contiguous blockIdx prefix
    const int b   = blockIdx.x & 7;
    const int l   = blockIdx.x >> 3;
    const int row = (b << 7) | l;
    const int tid = threadIdx.x;

    __shared__ unsigned long long s_key[NT / 32];
    __shared__ int s_src, s_nn;
    __shared__ int s_red[NT];

    if (rwrt[row]) {
        const float* lp = logits + (size_t)row * VFc;
        const float* gp = gumbel + (size_t)row * VFc;

        unsigned long long key;
        if (b < 2) argmax_body<true >(lp, gp, tid, key);  // pin batches 0,1 logits
        else       argmax_body<false>(lp, gp, tid, key);  // stream logits

        #pragma unroll
        for (int off = 16; off > 0; off >>= 1) {
            const unsigned long long o = __shfl_down_sync(0xffffffffu, key, off);
            if (o > key) key = o;
        }
        if ((tid & 31) == 0) s_key[tid >> 5] = key;
        __syncthreads();
        if (tid == 0) {
            #pragma unroll
            for (int w = 1; w < NT / 32; w++)
                if (s_key[w] > key) key = s_key[w];
            const int g = (int)(~(unsigned)(key & 0xffffffffu));
            s_src = (g < Vc) ? g : -1;   // g >= V => zero row (g[..., :V])
            s_nn  = (g < Vc) ? g : 0;    // zero row => sims all 0 => argmax 0
        }
        __syncthreads();
    } else {
        // ---- psg path: len[b] = sum of prefix mask ----
        s_red[tid] = (tid < Lc) ? rwrt[b * Lc + tid] : 0;
        __syncthreads();
        #pragma unroll
        for (int s = NT / 2; s > 0; s >>= 1) {
            if (tid < s) s_red[tid] += s_red[tid + s];
            __syncthreads();
        }
        if (tid == 0) {
            const int len = s_red[0];
            const int idx = psg[b * Lc + (l - len)];
            s_src = idx;
            s_nn  = idx;
        }
        __syncthreads();
    }

    // ---- write embeds row: 96 threads x 32B; gather pinned, store streaming ----
    const int src = s_src;
    float* orow = out + (size_t)row * Dc;
    if (tid < Dc / 8) {               // 96 threads
        f8 d;
        if (src >= 0) {
            d = ld32_last(wemb + (size_t)src * Dc + tid * 8);   // reused per replay
        } else {
            #pragma unroll
            for (int e = 0; e < 8; e++) d.v[e] = 0.f;
        }
        st32_stream(orow + tid * 8, d);   // output: evict-first
    }
    if (tid == 0)
        out[(size_t)NROWS * Dc + row] = (float)s_nn;
}

extern "C" void kernel_launch(void* const* d_in, const int* in_sizes, int n_in,
                              void* d_out, int out_size) {
    const float* logits = (const float*)d_in[0];
    const float* gumbel = (const float*)d_in[1];
    const float* wemb   = (const float*)d_in[2];
    const int*   rwrt   = (const int*)d_in[3];
    const int*   psg    = (const int*)d_in[4];
    float*       out    = (float*)d_out;

    fused_gsm_embed_nn<<<NROWS, NT>>>(logits, gumbel, wemb, rwrt, psg, out);
}